// round 11
// baseline (speedup 1.0000x reference)
#include <cuda_runtime.h>
#include <cstdint>
#include <cstddef>

#define BB 8
#define MM 8192
#define DD 256
#define HOPS 3

// Scratch (allocation-free __device__ globals)
__device__ float g_o[BB * DD];        // cumulative sum of o_k across hops (u = q + g_o)
__device__ float g_logits[BB * MM];
__device__ float g_pmax[BB * 128];
__device__ float g_psum[BB * 128];
__device__ float g_bmax[BB];
__device__ float g_binv[BB];

// ---------------- PTX helpers: mbarrier + 1-D bulk copy ----------------
__device__ __forceinline__ uint32_t smem_u32(const void* p) {
    uint32_t a;
    asm("{ .reg .u64 t; cvta.to.shared.u64 t, %1; cvt.u32.u64 %0, t; }"
        : "=r"(a) : "l"(p));
    return a;
}
#define MBAR_INIT(addr, cnt) \
    asm volatile("mbarrier.init.shared.b64 [%0], %1;" :: "r"(addr), "r"(cnt) : "memory")
#define MBAR_EXPECT(addr, bytes) \
    asm volatile("mbarrier.arrive.expect_tx.shared.b64 _, [%0], %1;" :: "r"(addr), "r"(bytes) : "memory")
#define BULK_G2S(dst, src, bytes, mbar) \
    asm volatile("cp.async.bulk.shared::cluster.global.mbarrier::complete_tx::bytes [%0], [%1], %2, [%3];" \
                 :: "r"(dst), "l"(src), "r"(bytes), "r"(mbar) : "memory")
__device__ __forceinline__ void mbar_wait(uint32_t mbar, uint32_t parity) {
    asm volatile(
        "{\n\t.reg .pred P;\n\t"
        "W%=:\n\t"
        "mbarrier.try_wait.parity.shared.b64 P, [%0], %1;\n\t"
        "@!P bra W%=;\n\t}"
        :: "r"(mbar), "r"(parity) : "memory");
}

#define STAGES 4
#define SROWS  8                       // rows per stage
#define SBYTES (SROWS * DD * 4)        // 8 KB
#define NITER  8                       // 64 rows / 8

// ---------------------------------------------------------------------------
// K0: zero the cumulative o accumulator
// ---------------------------------------------------------------------------
__global__ void k_init() {
    g_o[blockIdx.x * 256 + threadIdx.x] = 0.0f;
}

// ---------------------------------------------------------------------------
// K1: logits[b,m] = gp[b,m] * dot(ms[b,m,:], q[b,:]+g_o[b,:])  + block stats.
// TMA-staged: 4-stage smem ring fed by cp.async.bulk; warp w consumes stage
// row w (8 warps x 8 stages = 64 rows/CTA). Epilogue identical to R8.
// ---------------------------------------------------------------------------
__global__ void __launch_bounds__(256)
k_logits(const float* __restrict__ ms,
         const float* __restrict__ q,
         const float* __restrict__ gp,
         float* __restrict__ out_logits) {
    const int ROWS = 64;
    int row0 = blockIdx.x * ROWS;
    int b = row0 >> 13;
    int lane = threadIdx.x & 31;
    int warp = threadIdx.x >> 5;

    __shared__ __align__(128) float sbuf[STAGES][SROWS * DD];   // 32 KB
    __shared__ float su[DD];
    __shared__ float srow[ROWS];
    __shared__ __align__(8) uint64_t mbar[STAGES];

    su[threadIdx.x] = q[b * DD + threadIdx.x] + g_o[b * DD + threadIdx.x];
    if (threadIdx.x == 0)
        for (int s = 0; s < STAGES; s++) MBAR_INIT(smem_u32(&mbar[s]), 1);
    __syncthreads();

    const float* base = ms + (size_t)row0 * DD;
    if (threadIdx.x == 0) {
#pragma unroll
        for (int p = 0; p < 3; p++) {                 // 3-deep prologue
            uint32_t mb = smem_u32(&mbar[p]);
            MBAR_EXPECT(mb, SBYTES);
            BULK_G2S(smem_u32(sbuf[p]), base + (size_t)p * SROWS * DD, SBYTES, mb);
        }
    }

    float4 ub0 = reinterpret_cast<const float4*>(su)[lane];
    float4 ub1 = reinterpret_cast<const float4*>(su)[lane + 32];

    for (int i = 0; i < NITER; i++) {
        int s = i & 3;
        mbar_wait(smem_u32(&mbar[s]), (i >> 2) & 1);

        // warp w handles stage row w
        const float4* rp = reinterpret_cast<const float4*>(sbuf[s] + warp * DD);
        float4 a0 = rp[lane];
        float4 a1 = rp[lane + 32];
        float v = a0.x * ub0.x + a0.y * ub0.y + a0.z * ub0.z + a0.w * ub0.w
                + a1.x * ub1.x + a1.y * ub1.y + a1.z * ub1.z + a1.w * ub1.w;
#pragma unroll
        for (int off = 16; off; off >>= 1)
            v += __shfl_xor_sync(0xffffffffu, v, off);
        if (lane == 0) {
            int row = row0 + i * SROWS + warp;
            float l = v * gp[row];
            g_logits[row] = l;
            srow[i * SROWS + warp] = l;
            if (out_logits) out_logits[row] = l;
        }
        __syncthreads();                               // stage consumed

        if (threadIdx.x == 0 && i + 3 < NITER) {
            int p = i + 3, s2 = p & 3;
            uint32_t mb = smem_u32(&mbar[s2]);
            MBAR_EXPECT(mb, SBYTES);
            BULK_G2S(smem_u32(sbuf[s2]), base + (size_t)p * SROWS * DD, SBYTES, mb);
        }
    }

    // Block-local softmax stats over the 64 logits (warp 0)
    if (warp == 0) {
        float v0 = srow[lane];
        float v1 = srow[lane + 32];
        float m = fmaxf(v0, v1);
#pragma unroll
        for (int off = 16; off; off >>= 1)
            m = fmaxf(m, __shfl_xor_sync(0xffffffffu, m, off));
        float sum = __expf(v0 - m) + __expf(v1 - m);
#pragma unroll
        for (int off = 16; off; off >>= 1)
            sum += __shfl_xor_sync(0xffffffffu, sum, off);
        if (lane == 0) {
            g_pmax[blockIdx.x] = m;
            g_psum[blockIdx.x] = sum;
        }
    }
}

// ---------------------------------------------------------------------------
// K2: merge 128 partial (max,sum) pairs per b -> (bmax, 1/sum). 1 CTA.
// ---------------------------------------------------------------------------
__global__ void k_combine() {
    int b = threadIdx.x >> 5;
    int lane = threadIdx.x & 31;
    float m = -1e30f, s = 0.0f;
#pragma unroll
    for (int i = 0; i < 4; i++) {
        int idx = b * 128 + i * 32 + lane;
        float pm = g_pmax[idx], ps = g_psum[idx];
        float nm = fmaxf(m, pm);
        s = s * __expf(m - nm) + ps * __expf(pm - nm);
        m = nm;
    }
#pragma unroll
    for (int off = 16; off; off >>= 1) {
        float om = __shfl_xor_sync(0xffffffffu, m, off);
        float os = __shfl_xor_sync(0xffffffffu, s, off);
        float nm = fmaxf(m, om);
        s = s * __expf(m - nm) + os * __expf(om - nm);
        m = nm;
    }
    if (lane == 0) {
        g_bmax[b] = m;
        g_binv[b] = 1.0f / s;
    }
}

// ---------------------------------------------------------------------------
// K3: o[b,:] += sum_m softmax(l)[m]*gp[m]*ms[b,m,:]
// TMA-staged ring; consumer keeps R8's mapping: c=tid&63 (float4 col),
// g=tid>>6 (row group): per stage, thread does stage rows g and g+4.
// Epilogue identical to R8 (sred + 64-thread atomics).
// ---------------------------------------------------------------------------
__global__ void __launch_bounds__(256)
k_ok(const float* __restrict__ ms, const float* __restrict__ gp) {
    const int CHUNK = 64;
    int row0 = blockIdx.x * CHUNK;
    int b = row0 >> 13;
    int c = threadIdx.x & 63;
    int g = threadIdx.x >> 6;

    __shared__ __align__(128) float sbuf[STAGES][SROWS * DD];   // 32 KB
    __shared__ float sw[CHUNK];
    __shared__ float4 sred[4][64];
    __shared__ __align__(8) uint64_t mbar[STAGES];

    if (threadIdx.x < CHUNK) {
        int r = row0 + threadIdx.x;
        sw[threadIdx.x] = __expf(g_logits[r] - g_bmax[b]) * g_binv[b] * gp[r];
    }
    if (threadIdx.x == 0)
        for (int s = 0; s < STAGES; s++) MBAR_INIT(smem_u32(&mbar[s]), 1);
    __syncthreads();

    const float* base = ms + (size_t)row0 * DD;
    if (threadIdx.x == 0) {
#pragma unroll
        for (int p = 0; p < 3; p++) {
            uint32_t mb = smem_u32(&mbar[p]);
            MBAR_EXPECT(mb, SBYTES);
            BULK_G2S(smem_u32(sbuf[p]), base + (size_t)p * SROWS * DD, SBYTES, mb);
        }
    }

    float4 acc0 = make_float4(0.f, 0.f, 0.f, 0.f);
    float4 acc1 = make_float4(0.f, 0.f, 0.f, 0.f);

    for (int i = 0; i < NITER; i++) {
        int s = i & 3;
        mbar_wait(smem_u32(&mbar[s]), (i >> 2) & 1);

        const float4* sp = reinterpret_cast<const float4*>(sbuf[s]);
        float4 a0 = sp[(g    ) * 64 + c];
        float4 a1 = sp[(g + 4) * 64 + c];
        float w0 = sw[i * SROWS + g];
        float w1 = sw[i * SROWS + g + 4];
        acc0.x = fmaf(w0, a0.x, acc0.x); acc1.x = fmaf(w1, a1.x, acc1.x);
        acc0.y = fmaf(w0, a0.y, acc0.y); acc1.y = fmaf(w1, a1.y, acc1.y);
        acc0.z = fmaf(w0, a0.z, acc0.z); acc1.z = fmaf(w1, a1.z, acc1.z);
        acc0.w = fmaf(w0, a0.w, acc0.w); acc1.w = fmaf(w1, a1.w, acc1.w);
        __syncthreads();                               // stage consumed

        if (threadIdx.x == 0 && i + 3 < NITER) {
            int p = i + 3, s2 = p & 3;
            uint32_t mb = smem_u32(&mbar[s2]);
            MBAR_EXPECT(mb, SBYTES);
            BULK_G2S(smem_u32(sbuf[s2]), base + (size_t)p * SROWS * DD, SBYTES, mb);
        }
    }

    acc0.x += acc1.x; acc0.y += acc1.y; acc0.z += acc1.z; acc0.w += acc1.w;
    sred[g][c] = acc0;
    __syncthreads();

    if (g == 0) {
        float4 r0 = sred[0][c], r1 = sred[1][c], r2 = sred[2][c], r3 = sred[3][c];
        float* o = g_o + b * DD + c * 4;
        atomicAdd(o + 0, r0.x + r1.x + r2.x + r3.x);
        atomicAdd(o + 1, r0.y + r1.y + r2.y + r3.y);
        atomicAdd(o + 2, r0.z + r1.z + r2.z + r3.z);
        atomicAdd(o + 3, r0.w + r1.w + r2.w + r3.w);
    }
}

// ---------------------------------------------------------------------------
// K4 (last hop only): prob_soft = softmax(logits)
// ---------------------------------------------------------------------------
__global__ void k_prob(float* __restrict__ out_prob) {
    int i = blockIdx.x * 256 + threadIdx.x;
    int b = i >> 13;
    out_prob[i] = __expf(g_logits[i] - g_bmax[b]) * g_binv[b];
}

// ---------------------------------------------------------------------------
extern "C" void kernel_launch(void* const* d_in, const int* in_sizes, int n_in,
                              void* d_out, int out_size) {
    const float* q  = (const float*)d_in[0];   // (8,256)
    const float* gp = (const float*)d_in[1];   // (8,8192)
    const float* ms = (const float*)d_in[2];   // (4,8,8192,256)

    float* out        = (float*)d_out;
    float* out_prob   = out;
    float* out_logits = out + BB * MM;

    const size_t SLICE = (size_t)BB * MM * DD;

    k_init<<<8, 256>>>();

    for (int h = 0; h < HOPS; h++) {
        bool last = (h == HOPS - 1);
        k_logits<<<BB * MM / 64, 256>>>(ms + (size_t)h * SLICE, q, gp,
                                        last ? out_logits : nullptr);
        k_combine<<<1, 256>>>();
        if (!last) {
            k_ok<<<BB * MM / 64, 256>>>(ms + (size_t)(h + 1) * SLICE, gp);
        } else {
            k_prob<<<BB * MM / 256, 256>>>(out_prob);
        }
    }
}